// round 7
// baseline (speedup 1.0000x reference)
#include <cuda_runtime.h>
#include <cuda_bf16.h>

#define NN 25000
#define NR 16
#define NH 64
#define NC 16
#define NE 800000
#define CHUNK 1000          // NN = 25 * 1000
#define NCHUNK 25

// ---- scratch (allocation-free: __device__ globals; zero-initialized) ----
__device__ float g_x[NN * NH];                 // layer-1 output x = relu(agg1+root1+b1)
__device__ float g_h[(size_t)NR * NN * NC];    // per-relation transformed nodes
__device__ int   g_rowidx[NE];                 // rel*NN + src (row into W1 and into h)
__device__ int   g_dstv[NE];
__device__ int   g_lrank[NE];                  // rank of edge within its dst bucket
__device__ int   g_deg[NN];                    // invariant: 0 at launch entry
__device__ int   g_offL[NN];                   // chunk-local exclusive scan of deg
__device__ int   g_boff[NCHUNK];               // chunk base offsets
__device__ int   g_pref[NCHUNK];               // inclusive chunk prefix (internal)
__device__ volatile int g_flag[NCHUNK];        // invariant: 0 at launch entry
__device__ int   g_csr[NE];                    // rowidx grouped by dst

__device__ __forceinline__ int final_off(int i) {
    return (i < NN) ? (g_offL[i] + g_boff[i / CHUNK]) : NE;
}

// ---------------------------------------------------------------------------
// Convert edge metadata (4 edges/thread, vector loads) + histogram + rank.
// dtype detect done per-block (L2-hit reads, one-time ~600cyc, overlapped).
__global__ void k_convert(const void* ei, const void* et) {
    __shared__ int s_is64;
    if (threadIdx.x == 0) {
        const unsigned long long* p = (const unsigned long long*)ei;
        unsigned long long acc = 0;
#pragma unroll
        for (int i = 0; i < 32; i++) acc |= (p[i] >> 32);
        s_is64 = (acc == 0ull) ? 1 : 0;
    }
    __syncthreads();
    int e4 = blockIdx.x * blockDim.x + threadIdx.x;
    if (e4 >= NE / 4) return;
    int e = e4 * 4;

    int src[4], dst[4], rel[4];
    if (s_is64) {
        const longlong2* E = (const longlong2*)ei;
        const longlong2* T = (const longlong2*)et;
        longlong2 s0 = __ldg(&E[e / 2]),          s1 = __ldg(&E[e / 2 + 1]);
        longlong2 d0 = __ldg(&E[(NE + e) / 2]),   d1 = __ldg(&E[(NE + e) / 2 + 1]);
        longlong2 t0 = __ldg(&T[e / 2]),          t1 = __ldg(&T[e / 2 + 1]);
        src[0] = (int)s0.x; src[1] = (int)s0.y; src[2] = (int)s1.x; src[3] = (int)s1.y;
        dst[0] = (int)d0.x; dst[1] = (int)d0.y; dst[2] = (int)d1.x; dst[3] = (int)d1.y;
        rel[0] = (int)t0.x; rel[1] = (int)t0.y; rel[2] = (int)t1.x; rel[3] = (int)t1.y;
    } else {
        const int* Ei = (const int*)ei;
        const int* Ti = (const int*)et;
        int4 s = __ldg((const int4*)(Ei + e));
        int4 d = __ldg((const int4*)(Ei + NE + e));
        int4 t = __ldg((const int4*)(Ti + e));
        src[0] = s.x; src[1] = s.y; src[2] = s.z; src[3] = s.w;
        dst[0] = d.x; dst[1] = d.y; dst[2] = d.z; dst[3] = d.w;
        rel[0] = t.x; rel[1] = t.y; rel[2] = t.z; rel[3] = t.w;
    }
    int4 rw, lr;
    rw.x = rel[0] * NN + src[0]; rw.y = rel[1] * NN + src[1];
    rw.z = rel[2] * NN + src[2]; rw.w = rel[3] * NN + src[3];
    lr.x = atomicAdd(&g_deg[dst[0]], 1);
    lr.y = atomicAdd(&g_deg[dst[1]], 1);
    lr.z = atomicAdd(&g_deg[dst[2]], 1);
    lr.w = atomicAdd(&g_deg[dst[3]], 1);
    *(int4*)(g_rowidx + e) = rw;
    *(int4*)(g_dstv + e)   = make_int4(dst[0], dst[1], dst[2], dst[3]);
    *(int4*)(g_lrank + e)  = lr;
}

// Single-pass scan: 25 blocks, local scan + chained prefix handoff.
// Also re-zeroes g_deg (restores launch-entry invariant for graph replay).
__global__ void k_scan1() {
    __shared__ int warp_sums[32];
    __shared__ int s_total;
    int tid  = threadIdx.x;            // 1024 threads
    int lane = tid & 31;
    int wid  = tid >> 5;
    int b    = blockIdx.x;
    int idx  = b * CHUNK + tid;
    int v = (tid < CHUNK) ? g_deg[idx] : 0;
    if (tid < CHUNK) g_deg[idx] = 0;
    int incl = v;
#pragma unroll
    for (int d = 1; d < 32; d <<= 1) {
        int t = __shfl_up_sync(0xFFFFFFFFu, incl, d);
        if (lane >= d) incl += t;
    }
    if (lane == 31) warp_sums[wid] = incl;
    __syncthreads();
    if (wid == 0) {
        int ws = warp_sums[lane];
#pragma unroll
        for (int d = 1; d < 32; d <<= 1) {
            int t = __shfl_up_sync(0xFFFFFFFFu, ws, d);
            if (lane >= d) ws += t;
        }
        warp_sums[lane] = ws;
        if (lane == 31) s_total = ws;
    }
    __syncthreads();
    int excl = incl - v + (wid > 0 ? warp_sums[wid - 1] : 0);
    if (tid < CHUNK) g_offL[idx] = excl;

    if (tid == 0) {
        int total = s_total;
        int pref;
        if (b == 0) {
            pref = 0;
        } else {
            while (g_flag[b - 1] == 0) { }
            __threadfence();
            pref = g_pref[b - 1];
        }
        g_boff[b] = pref;
        g_pref[b] = pref + total;
        __threadfence();
        g_flag[b] = 1;
    }
}

// Scatter rowidx into CSR order — no atomics (rank precomputed), 4 edges/thread.
// Also re-zeroes g_flag for the next replay.
__global__ void k_scatter() {
    if (blockIdx.x == 0 && threadIdx.x < NCHUNK) g_flag[threadIdx.x] = 0;
    int e4 = blockIdx.x * blockDim.x + threadIdx.x;
    if (e4 >= NE / 4) return;
    int e = e4 * 4;
    int4 rw = __ldg((const int4*)(g_rowidx + e));
    int4 dv = __ldg((const int4*)(g_dstv + e));
    int4 lr = __ldg((const int4*)(g_lrank + e));
    g_csr[g_offL[dv.x] + g_boff[dv.x / CHUNK] + lr.x] = rw.x;
    g_csr[g_offL[dv.y] + g_boff[dv.y / CHUNK] + lr.y] = rw.y;
    g_csr[g_offL[dv.z] + g_boff[dv.z / CHUNK] + lr.z] = rw.z;
    g_csr[g_offL[dv.w] + g_boff[dv.w / CHUNK] + lr.w] = rw.w;
}

// Layer-1 aggregation: 16 threads per dst, register accumulation.
// Index stream read as int4 (peel to 16B alignment first).
__global__ void k_agg1(const float* __restrict__ W1,
                       const float* __restrict__ root1,
                       const float* __restrict__ b1) {
    int g = blockIdx.x * (blockDim.x >> 4) + (threadIdx.x >> 4);
    int s = threadIdx.x & 15;
    if (g >= NN) return;
    int beg = final_off(g), end = final_off(g + 1);

    float4 acc = make_float4(0.f, 0.f, 0.f, 0.f);
    int i = beg;
    // peel to 4-alignment
    for (; i < end && (i & 3); i++) {
        float4 v0 = __ldg((const float4*)(W1 + (long)g_csr[i] * NH) + s);
        acc.x += v0.x; acc.y += v0.y; acc.z += v0.z; acc.w += v0.w;
    }
    for (; i + 8 <= end; i += 8) {
        int4 c0 = __ldg((const int4*)(g_csr + i));
        int4 c1 = __ldg((const int4*)(g_csr + i + 4));
        float4 v0 = __ldg((const float4*)(W1 + (long)c0.x * NH) + s);
        float4 v1 = __ldg((const float4*)(W1 + (long)c0.y * NH) + s);
        float4 v2 = __ldg((const float4*)(W1 + (long)c0.z * NH) + s);
        float4 v3 = __ldg((const float4*)(W1 + (long)c0.w * NH) + s);
        float4 v4 = __ldg((const float4*)(W1 + (long)c1.x * NH) + s);
        float4 v5 = __ldg((const float4*)(W1 + (long)c1.y * NH) + s);
        float4 v6 = __ldg((const float4*)(W1 + (long)c1.z * NH) + s);
        float4 v7 = __ldg((const float4*)(W1 + (long)c1.w * NH) + s);
        acc.x += (v0.x + v1.x) + (v2.x + v3.x) + (v4.x + v5.x) + (v6.x + v7.x);
        acc.y += (v0.y + v1.y) + (v2.y + v3.y) + (v4.y + v5.y) + (v6.y + v7.y);
        acc.z += (v0.z + v1.z) + (v2.z + v3.z) + (v4.z + v5.z) + (v6.z + v7.z);
        acc.w += (v0.w + v1.w) + (v2.w + v3.w) + (v4.w + v5.w) + (v6.w + v7.w);
    }
    for (; i < end; i++) {
        float4 v0 = __ldg((const float4*)(W1 + (long)g_csr[i] * NH) + s);
        acc.x += v0.x; acc.y += v0.y; acc.z += v0.z; acc.w += v0.w;
    }
    float4 rt = __ldg((const float4*)(root1 + (long)g * NH) + s);
    float4 bb = __ldg((const float4*)b1 + s);
    acc.x = fmaxf(acc.x + rt.x + bb.x, 0.f);
    acc.y = fmaxf(acc.y + rt.y + bb.y, 0.f);
    acc.z = fmaxf(acc.z + rt.z + bb.z, 0.f);
    acc.w = fmaxf(acc.w + rt.w + bb.w, 0.f);
    *((float4*)(g_x + (long)g * NH) + s) = acc;
}

// ---------------------------------------------------------------------------
// h[r,n,c] = sum_h x[n,h] * W2[r,h,c]  — f32x2 version.
#define HT 64   // nodes per tile
__global__ void __launch_bounds__(256) k_h2(const float* __restrict__ W2) {
    __shared__ unsigned long long xs[HT * (NH / 2)];   // 16 KB

    int tid  = threadIdx.x;
    int lane = tid & 31;
    int w    = tid >> 5;
    int r    = w * 2 + (lane >> 4);
    int c    = lane & 15;

    unsigned long long wp[NH / 2];
    const float* w2r = W2 + (long)r * NH * NC + c;
#pragma unroll
    for (int j = 0; j < NH / 2; j++) {
        float we = __ldg(w2r + (2 * j) * NC);
        float wo = __ldg(w2r + (2 * j + 1) * NC);
        asm("mov.b64 %0, {%1, %2};" : "=l"(wp[j]) : "f"(we), "f"(wo));
    }

    int nbase = blockIdx.x * HT;
    const unsigned long long* gx8 = (const unsigned long long*)g_x;
    long gbase = (long)nbase * (NH / 2);
    for (int i = tid; i < HT * (NH / 2); i += 256) {
        long gi = gbase + i;
        xs[i] = (gi < (long)NN * (NH / 2)) ? gx8[gi] : 0ull;
    }
    __syncthreads();

    int nvalid = NN - nbase; if (nvalid > HT) nvalid = HT;
    for (int j = 0; j < nvalid; j++) {
        const unsigned long long* xrow = xs + j * (NH / 2);
        unsigned long long a0 = 0ull, a1 = 0ull;
#pragma unroll
        for (int k = 0; k < NH / 4; k++) {
            unsigned long long x0 = xrow[2 * k];
            unsigned long long x1 = xrow[2 * k + 1];
            asm("fma.rn.f32x2 %0, %1, %2, %0;" : "+l"(a0) : "l"(x0), "l"(wp[2 * k]));
            asm("fma.rn.f32x2 %0, %1, %2, %0;" : "+l"(a1) : "l"(x1), "l"(wp[2 * k + 1]));
        }
        unsigned long long asum;
        asm("add.rn.f32x2 %0, %1, %2;" : "=l"(asum) : "l"(a0), "l"(a1));
        float lo, hi;
        asm("mov.b64 {%0, %1}, %2;" : "=f"(lo), "=f"(hi) : "l"(asum));
        g_h[((long)r * NN + (nbase + j)) * NC + c] = lo + hi;
    }
}

// Layer-2 aggregation + root + bias + log_softmax, fused. 16 threads per dst.
__global__ void k_agg2(const float* __restrict__ root2,
                       const float* __restrict__ b2,
                       float* __restrict__ out) {
    __shared__ float r2s[NH * NC];
    for (int i = threadIdx.x; i < NH * NC; i += blockDim.x) r2s[i] = root2[i];
    __syncthreads();

    int g = blockIdx.x * (blockDim.x >> 4) + (threadIdx.x >> 4);
    int c = threadIdx.x & 15;
    if (g >= NN) return;
    int beg = final_off(g), end = final_off(g + 1);

    float acc = __ldg(b2 + c);
    int i = beg;
    for (; i < end && (i & 3); i++)
        acc += __ldg(g_h + (long)g_csr[i] * NC + c);
    for (; i + 8 <= end; i += 8) {
        int4 c0 = __ldg((const int4*)(g_csr + i));
        int4 c1 = __ldg((const int4*)(g_csr + i + 4));
        float v0 = __ldg(g_h + (long)c0.x * NC + c);
        float v1 = __ldg(g_h + (long)c0.y * NC + c);
        float v2 = __ldg(g_h + (long)c0.z * NC + c);
        float v3 = __ldg(g_h + (long)c0.w * NC + c);
        float v4 = __ldg(g_h + (long)c1.x * NC + c);
        float v5 = __ldg(g_h + (long)c1.y * NC + c);
        float v6 = __ldg(g_h + (long)c1.z * NC + c);
        float v7 = __ldg(g_h + (long)c1.w * NC + c);
        acc += ((v0 + v1) + (v2 + v3)) + ((v4 + v5) + (v6 + v7));
    }
    for (; i < end; i++)
        acc += __ldg(g_h + (long)g_csr[i] * NC + c);

    const float4* xr = (const float4*)(g_x + (long)g * NH);
#pragma unroll
    for (int h4 = 0; h4 < NH / 4; h4++) {
        float4 xv = __ldg(&xr[h4]);
        acc += xv.x * r2s[(h4 * 4 + 0) * NC + c];
        acc += xv.y * r2s[(h4 * 4 + 1) * NC + c];
        acc += xv.z * r2s[(h4 * 4 + 2) * NC + c];
        acc += xv.w * r2s[(h4 * 4 + 3) * NC + c];
    }

    unsigned mask = 0xFFFFu << (threadIdx.x & 16);
    float m = acc;
#pragma unroll
    for (int d = 8; d >= 1; d >>= 1) m = fmaxf(m, __shfl_xor_sync(mask, m, d));
    float ex = expf(acc - m);
    float sum = ex;
#pragma unroll
    for (int d = 8; d >= 1; d >>= 1) sum += __shfl_xor_sync(mask, sum, d);
    out[(long)g * NC + c] = acc - m - logf(sum);
}

extern "C" void kernel_launch(void* const* d_in, const int* in_sizes, int n_in,
                              void* d_out, int out_size) {
    const void*  edge_index = d_in[0];
    const void*  edge_type  = d_in[1];
    const float* W1         = (const float*)d_in[2];
    const float* root1      = (const float*)d_in[3];
    const float* b1         = (const float*)d_in[4];
    const float* W2         = (const float*)d_in[5];
    const float* root2      = (const float*)d_in[6];
    const float* b2         = (const float*)d_in[7];
    float* out = (float*)d_out;

    k_convert<<<(NE / 4 + 255) / 256, 256>>>(edge_index, edge_type);
    k_scan1<<<NCHUNK, 1024>>>();
    k_scatter<<<(NE / 4 + 255) / 256, 256>>>();
    k_agg1<<<(NN * 16 + 255) / 256, 256>>>(W1, root1, b1);
    k_h2<<<(NN + HT - 1) / HT, 256>>>(W2);
    k_agg2<<<(NN * 16 + 255) / 256, 256>>>(root2, b2, out);
}

// round 9
// speedup vs baseline: 1.0368x; 1.0368x over previous
#include <cuda_runtime.h>
#include <cuda_bf16.h>

#define NN 25000
#define NR 16
#define NH 64
#define NC 16
#define NE 800000
#define CHUNK 1000          // NN = 25 * 1000
#define NCHUNK 25

// ---- scratch (allocation-free: __device__ globals; zero-initialized) ----
__device__ float g_x[NN * NH];                 // layer-1 output x = relu(agg1+root1+b1)
__device__ float g_h[(size_t)NR * NN * NC];    // per-relation transformed nodes
__device__ int   g_deg[NN];                    // invariant: 0 at launch entry
__device__ int   g_off[NN + 1];                // final CSR offsets
__device__ int   g_cur[NN];                    // scatter cursors (consumed each pass)
__device__ int   g_pref[NCHUNK];               // inclusive chunk prefix (internal)
__device__ volatile int g_flag[NCHUNK];        // invariant: 0 at launch entry
__device__ int   g_csr[NE];                    // rel*NN+src grouped by dst

// ---------------------------------------------------------------------------
// Histogram dst degrees. Reads ONLY the dst half of edge_index.
// dtype detect per-block from the src half (L2-hit after first block).
__global__ void k_hist(const void* ei) {
    __shared__ int s_is64;
    if (threadIdx.x == 0) {
        const unsigned long long* p = (const unsigned long long*)ei;
        unsigned long long acc = 0;
#pragma unroll
        for (int i = 0; i < 32; i++) acc |= (p[i] >> 32);
        s_is64 = (acc == 0ull) ? 1 : 0;
    }
    __syncthreads();
    int e4 = blockIdx.x * blockDim.x + threadIdx.x;
    if (e4 >= NE / 4) return;
    int e = e4 * 4;
    int d0, d1, d2, d3;
    if (s_is64) {
        const longlong2* E = (const longlong2*)ei;
        longlong2 a = __ldg(&E[(NE + e) / 2]);
        longlong2 b = __ldg(&E[(NE + e) / 2 + 1]);
        d0 = (int)a.x; d1 = (int)a.y; d2 = (int)b.x; d3 = (int)b.y;
    } else {
        int4 d = __ldg((const int4*)((const int*)ei + NE + e));
        d0 = d.x; d1 = d.y; d2 = d.z; d3 = d.w;
    }
    atomicAdd(&g_deg[d0], 1);
    atomicAdd(&g_deg[d1], 1);
    atomicAdd(&g_deg[d2], 1);
    atomicAdd(&g_deg[d3], 1);
}

// Single-pass scan: 25 blocks, chained prefix handoff.  Writes FINAL offsets
// into g_off and g_cur.  Re-zeroes g_deg (restores replay invariant).
__global__ void k_scan1() {
    __shared__ int warp_sums[32];
    __shared__ int s_total, s_pref;
    int tid  = threadIdx.x;            // 1024 threads
    int lane = tid & 31;
    int wid  = tid >> 5;
    int b    = blockIdx.x;
    int idx  = b * CHUNK + tid;
    int v = (tid < CHUNK) ? g_deg[idx] : 0;
    if (tid < CHUNK) g_deg[idx] = 0;
    int incl = v;
#pragma unroll
    for (int d = 1; d < 32; d <<= 1) {
        int t = __shfl_up_sync(0xFFFFFFFFu, incl, d);
        if (lane >= d) incl += t;
    }
    if (lane == 31) warp_sums[wid] = incl;
    __syncthreads();
    if (wid == 0) {
        int ws = warp_sums[lane];
#pragma unroll
        for (int d = 1; d < 32; d <<= 1) {
            int t = __shfl_up_sync(0xFFFFFFFFu, ws, d);
            if (lane >= d) ws += t;
        }
        warp_sums[lane] = ws;
        if (lane == 31) s_total = ws;
    }
    __syncthreads();
    int excl = incl - v + (wid > 0 ? warp_sums[wid - 1] : 0);

    if (tid == 0) {
        int total = s_total;
        int pref;
        if (b == 0) {
            pref = 0;
        } else {
            while (g_flag[b - 1] == 0) { }
            __threadfence();
            pref = g_pref[b - 1];
        }
        g_pref[b] = pref + total;
        __threadfence();
        g_flag[b] = 1;
        s_pref = pref;
        if (b == NCHUNK - 1) g_off[NN] = pref + total;
    }
    __syncthreads();
    int fin = excl + s_pref;
    if (tid < CHUNK) { g_off[idx] = fin; g_cur[idx] = fin; }
}

// Scatter: read edge data directly, cursor-atomic position, write CSR.
// Also re-zeroes g_flag for the next replay.
__global__ void k_scatter(const void* ei, const void* et) {
    __shared__ int s_is64;
    if (threadIdx.x == 0) {
        const unsigned long long* p = (const unsigned long long*)ei;
        unsigned long long acc = 0;
#pragma unroll
        for (int i = 0; i < 32; i++) acc |= (p[i] >> 32);
        s_is64 = (acc == 0ull) ? 1 : 0;
        if (blockIdx.x == 0) {
#pragma unroll
            for (int i = 0; i < NCHUNK; i++) g_flag[i] = 0;
        }
    }
    __syncthreads();
    int e4 = blockIdx.x * blockDim.x + threadIdx.x;
    if (e4 >= NE / 4) return;
    int e = e4 * 4;
    int src[4], dst[4], rel[4];
    if (s_is64) {
        const longlong2* E = (const longlong2*)ei;
        const longlong2* T = (const longlong2*)et;
        longlong2 s0 = __ldg(&E[e / 2]),        s1 = __ldg(&E[e / 2 + 1]);
        longlong2 d0 = __ldg(&E[(NE + e) / 2]), d1 = __ldg(&E[(NE + e) / 2 + 1]);
        longlong2 t0 = __ldg(&T[e / 2]),        t1 = __ldg(&T[e / 2 + 1]);
        src[0] = (int)s0.x; src[1] = (int)s0.y; src[2] = (int)s1.x; src[3] = (int)s1.y;
        dst[0] = (int)d0.x; dst[1] = (int)d0.y; dst[2] = (int)d1.x; dst[3] = (int)d1.y;
        rel[0] = (int)t0.x; rel[1] = (int)t0.y; rel[2] = (int)t1.x; rel[3] = (int)t1.y;
    } else {
        const int* Ei = (const int*)ei;
        const int* Ti = (const int*)et;
        int4 s = __ldg((const int4*)(Ei + e));
        int4 d = __ldg((const int4*)(Ei + NE + e));
        int4 t = __ldg((const int4*)(Ti + e));
        src[0] = s.x; src[1] = s.y; src[2] = s.z; src[3] = s.w;
        dst[0] = d.x; dst[1] = d.y; dst[2] = d.z; dst[3] = d.w;
        rel[0] = t.x; rel[1] = t.y; rel[2] = t.z; rel[3] = t.w;
    }
#pragma unroll
    for (int j = 0; j < 4; j++) {
        int pos = atomicAdd(&g_cur[dst[j]], 1);
        g_csr[pos] = rel[j] * NN + src[j];
    }
}

// Layer-1 aggregation: 16 threads per dst, register accumulation, unroll 8.
__global__ void k_agg1(const float* __restrict__ W1,
                       const float* __restrict__ root1,
                       const float* __restrict__ b1) {
    int g = blockIdx.x * (blockDim.x >> 4) + (threadIdx.x >> 4);
    int s = threadIdx.x & 15;
    if (g >= NN) return;
    int beg = g_off[g], end = g_off[g + 1];

    float4 acc = make_float4(0.f, 0.f, 0.f, 0.f);
    int i = beg;
    for (; i + 8 <= end; i += 8) {
        float4 v0 = __ldg((const float4*)(W1 + (long)g_csr[i + 0] * NH) + s);
        float4 v1 = __ldg((const float4*)(W1 + (long)g_csr[i + 1] * NH) + s);
        float4 v2 = __ldg((const float4*)(W1 + (long)g_csr[i + 2] * NH) + s);
        float4 v3 = __ldg((const float4*)(W1 + (long)g_csr[i + 3] * NH) + s);
        float4 v4 = __ldg((const float4*)(W1 + (long)g_csr[i + 4] * NH) + s);
        float4 v5 = __ldg((const float4*)(W1 + (long)g_csr[i + 5] * NH) + s);
        float4 v6 = __ldg((const float4*)(W1 + (long)g_csr[i + 6] * NH) + s);
        float4 v7 = __ldg((const float4*)(W1 + (long)g_csr[i + 7] * NH) + s);
        acc.x += (v0.x + v1.x) + (v2.x + v3.x) + (v4.x + v5.x) + (v6.x + v7.x);
        acc.y += (v0.y + v1.y) + (v2.y + v3.y) + (v4.y + v5.y) + (v6.y + v7.y);
        acc.z += (v0.z + v1.z) + (v2.z + v3.z) + (v4.z + v5.z) + (v6.z + v7.z);
        acc.w += (v0.w + v1.w) + (v2.w + v3.w) + (v4.w + v5.w) + (v6.w + v7.w);
    }
    for (; i < end; i++) {
        float4 v0 = __ldg((const float4*)(W1 + (long)g_csr[i] * NH) + s);
        acc.x += v0.x; acc.y += v0.y; acc.z += v0.z; acc.w += v0.w;
    }
    float4 rt = __ldg((const float4*)(root1 + (long)g * NH) + s);
    float4 bb = __ldg((const float4*)b1 + s);
    acc.x = fmaxf(acc.x + rt.x + bb.x, 0.f);
    acc.y = fmaxf(acc.y + rt.y + bb.y, 0.f);
    acc.z = fmaxf(acc.z + rt.z + bb.z, 0.f);
    acc.w = fmaxf(acc.w + rt.w + bb.w, 0.f);
    *((float4*)(g_x + (long)g * NH) + s) = acc;
}

// ---------------------------------------------------------------------------
// h[r,n,c] = sum_h x[n,h] * W2[r,h,c]  — f32x2 version.
#define HT 64   // nodes per tile
__global__ void __launch_bounds__(256) k_h2(const float* __restrict__ W2) {
    __shared__ unsigned long long xs[HT * (NH / 2)];   // 16 KB

    int tid  = threadIdx.x;
    int lane = tid & 31;
    int w    = tid >> 5;
    int r    = w * 2 + (lane >> 4);
    int c    = lane & 15;

    unsigned long long wp[NH / 2];
    const float* w2r = W2 + (long)r * NH * NC + c;
#pragma unroll
    for (int j = 0; j < NH / 2; j++) {
        float we = __ldg(w2r + (2 * j) * NC);
        float wo = __ldg(w2r + (2 * j + 1) * NC);
        asm("mov.b64 %0, {%1, %2};" : "=l"(wp[j]) : "f"(we), "f"(wo));
    }

    int nbase = blockIdx.x * HT;
    const unsigned long long* gx8 = (const unsigned long long*)g_x;
    long gbase = (long)nbase * (NH / 2);
    for (int i = tid; i < HT * (NH / 2); i += 256) {
        long gi = gbase + i;
        xs[i] = (gi < (long)NN * (NH / 2)) ? gx8[gi] : 0ull;
    }
    __syncthreads();

    int nvalid = NN - nbase; if (nvalid > HT) nvalid = HT;
    for (int j = 0; j < nvalid; j++) {
        const unsigned long long* xrow = xs + j * (NH / 2);
        unsigned long long a0 = 0ull, a1 = 0ull;
#pragma unroll
        for (int k = 0; k < NH / 4; k++) {
            unsigned long long x0 = xrow[2 * k];
            unsigned long long x1 = xrow[2 * k + 1];
            asm("fma.rn.f32x2 %0, %1, %2, %0;" : "+l"(a0) : "l"(x0), "l"(wp[2 * k]));
            asm("fma.rn.f32x2 %0, %1, %2, %0;" : "+l"(a1) : "l"(x1), "l"(wp[2 * k + 1]));
        }
        unsigned long long asum;
        asm("add.rn.f32x2 %0, %1, %2;" : "=l"(asum) : "l"(a0), "l"(a1));
        float lo, hi;
        asm("mov.b64 {%0, %1}, %2;" : "=f"(lo), "=f"(hi) : "l"(asum));
        g_h[((long)r * NN + (nbase + j)) * NC + c] = lo + hi;
    }
}

// Layer-2 aggregation + root + bias + log_softmax, fused. 16 threads per dst.
__global__ void k_agg2(const float* __restrict__ root2,
                       const float* __restrict__ b2,
                       float* __restrict__ out) {
    __shared__ float r2s[NH * NC];
    for (int i = threadIdx.x; i < NH * NC; i += blockDim.x) r2s[i] = root2[i];
    __syncthreads();

    int g = blockIdx.x * (blockDim.x >> 4) + (threadIdx.x >> 4);
    int c = threadIdx.x & 15;
    if (g >= NN) return;
    int beg = g_off[g], end = g_off[g + 1];

    float acc = __ldg(b2 + c);
    int i = beg;
    for (; i + 8 <= end; i += 8) {
        float v0 = __ldg(g_h + (long)g_csr[i + 0] * NC + c);
        float v1 = __ldg(g_h + (long)g_csr[i + 1] * NC + c);
        float v2 = __ldg(g_h + (long)g_csr[i + 2] * NC + c);
        float v3 = __ldg(g_h + (long)g_csr[i + 3] * NC + c);
        float v4 = __ldg(g_h + (long)g_csr[i + 4] * NC + c);
        float v5 = __ldg(g_h + (long)g_csr[i + 5] * NC + c);
        float v6 = __ldg(g_h + (long)g_csr[i + 6] * NC + c);
        float v7 = __ldg(g_h + (long)g_csr[i + 7] * NC + c);
        acc += ((v0 + v1) + (v2 + v3)) + ((v4 + v5) + (v6 + v7));
    }
    for (; i < end; i++)
        acc += __ldg(g_h + (long)g_csr[i] * NC + c);

    const float4* xr = (const float4*)(g_x + (long)g * NH);
#pragma unroll
    for (int h4 = 0; h4 < NH / 4; h4++) {
        float4 xv = __ldg(&xr[h4]);
        acc += xv.x * r2s[(h4 * 4 + 0) * NC + c];
        acc += xv.y * r2s[(h4 * 4 + 1) * NC + c];
        acc += xv.z * r2s[(h4 * 4 + 2) * NC + c];
        acc += xv.w * r2s[(h4 * 4 + 3) * NC + c];
    }

    unsigned mask = 0xFFFFu << (threadIdx.x & 16);
    float m = acc;
#pragma unroll
    for (int d = 8; d >= 1; d >>= 1) m = fmaxf(m, __shfl_xor_sync(mask, m, d));
    float ex = expf(acc - m);
    float sum = ex;
#pragma unroll
    for (int d = 8; d >= 1; d >>= 1) sum += __shfl_xor_sync(mask, sum, d);
    out[(long)g * NC + c] = acc - m - logf(sum);
}

extern "C" void kernel_launch(void* const* d_in, const int* in_sizes, int n_in,
                              void* d_out, int out_size) {
    const void*  edge_index = d_in[0];
    const void*  edge_type  = d_in[1];
    const float* W1         = (const float*)d_in[2];
    const float* root1      = (const float*)d_in[3];
    const float* b1         = (const float*)d_in[4];
    const float* W2         = (const float*)d_in[5];
    const float* root2      = (const float*)d_in[6];
    const float* b2         = (const float*)d_in[7];
    float* out = (float*)d_out;

    k_hist<<<(NE / 4 + 255) / 256, 256>>>(edge_index);
    k_scan1<<<NCHUNK, 1024>>>();
    k_scatter<<<(NE / 4 + 255) / 256, 256>>>(edge_index, edge_type);
    k_agg1<<<(NN * 16 + 255) / 256, 256>>>(W1, root1, b1);
    k_h2<<<(NN + HT - 1) / HT, 256>>>(W2);
    k_agg2<<<(NN * 16 + 255) / 256, 256>>>(root2, b2, out);
}

// round 10
// speedup vs baseline: 1.0390x; 1.0022x over previous
#include <cuda_runtime.h>
#include <cuda_bf16.h>

#define NN 25000
#define NR 16
#define NH 64
#define NC 16
#define NE 800000
#define CHUNK 1000          // NN = 25 * 1000
#define NCHUNK 25

// ---- scratch (allocation-free: __device__ globals; zero-initialized) ----
__device__ float g_x[NN * NH];                 // layer-1 output x = relu(agg1+root1+b1)
__device__ float g_h[(size_t)NR * NN * NC];    // per-relation transformed nodes
__device__ int   g_deg[NN];                    // invariant: 0 at launch entry
__device__ int   g_off[NN + 1];                // final CSR offsets
__device__ int   g_cur[NN];                    // scatter cursors (consumed each pass)
__device__ int   g_pref[NCHUNK];               // inclusive chunk prefix (internal)
__device__ volatile int g_flag[NCHUNK];        // invariant: 0 at launch entry
__device__ int   g_csr[NE];                    // rel*NN+src grouped by dst

// ---------------------------------------------------------------------------
// Histogram dst degrees. Reads ONLY the dst half of edge_index.
// dtype detect per-block from the src half (L2-hit after first block).
__global__ void k_hist(const void* ei) {
    __shared__ int s_is64;
    if (threadIdx.x == 0) {
        const unsigned long long* p = (const unsigned long long*)ei;
        unsigned long long acc = 0;
#pragma unroll
        for (int i = 0; i < 32; i++) acc |= (p[i] >> 32);
        s_is64 = (acc == 0ull) ? 1 : 0;
    }
    __syncthreads();
    int e4 = blockIdx.x * blockDim.x + threadIdx.x;
    if (e4 >= NE / 4) return;
    int e = e4 * 4;
    int d0, d1, d2, d3;
    if (s_is64) {
        const longlong2* E = (const longlong2*)ei;
        longlong2 a = __ldg(&E[(NE + e) / 2]);
        longlong2 b = __ldg(&E[(NE + e) / 2 + 1]);
        d0 = (int)a.x; d1 = (int)a.y; d2 = (int)b.x; d3 = (int)b.y;
    } else {
        int4 d = __ldg((const int4*)((const int*)ei + NE + e));
        d0 = d.x; d1 = d.y; d2 = d.z; d3 = d.w;
    }
    atomicAdd(&g_deg[d0], 1);
    atomicAdd(&g_deg[d1], 1);
    atomicAdd(&g_deg[d2], 1);
    atomicAdd(&g_deg[d3], 1);
}

// Single-pass scan: 25 blocks, chained prefix handoff.  Writes FINAL offsets
// into g_off and g_cur.  Re-zeroes g_deg (restores replay invariant).
__global__ void k_scan1() {
    __shared__ int warp_sums[32];
    __shared__ int s_total, s_pref;
    int tid  = threadIdx.x;            // 1024 threads
    int lane = tid & 31;
    int wid  = tid >> 5;
    int b    = blockIdx.x;
    int idx  = b * CHUNK + tid;
    int v = (tid < CHUNK) ? g_deg[idx] : 0;
    if (tid < CHUNK) g_deg[idx] = 0;
    int incl = v;
#pragma unroll
    for (int d = 1; d < 32; d <<= 1) {
        int t = __shfl_up_sync(0xFFFFFFFFu, incl, d);
        if (lane >= d) incl += t;
    }
    if (lane == 31) warp_sums[wid] = incl;
    __syncthreads();
    if (wid == 0) {
        int ws = warp_sums[lane];
#pragma unroll
        for (int d = 1; d < 32; d <<= 1) {
            int t = __shfl_up_sync(0xFFFFFFFFu, ws, d);
            if (lane >= d) ws += t;
        }
        warp_sums[lane] = ws;
        if (lane == 31) s_total = ws;
    }
    __syncthreads();
    int excl = incl - v + (wid > 0 ? warp_sums[wid - 1] : 0);

    if (tid == 0) {
        int total = s_total;
        int pref;
        if (b == 0) {
            pref = 0;
        } else {
            while (g_flag[b - 1] == 0) { }
            __threadfence();
            pref = g_pref[b - 1];
        }
        g_pref[b] = pref + total;
        __threadfence();
        g_flag[b] = 1;
        s_pref = pref;
        if (b == NCHUNK - 1) g_off[NN] = pref + total;
    }
    __syncthreads();
    int fin = excl + s_pref;
    if (tid < CHUNK) { g_off[idx] = fin; g_cur[idx] = fin; }
}

// Scatter: read edge data directly, cursor-atomic position, write CSR.
// Also re-zeroes g_flag for the next replay.
__global__ void k_scatter(const void* ei, const void* et) {
    __shared__ int s_is64;
    if (threadIdx.x == 0) {
        const unsigned long long* p = (const unsigned long long*)ei;
        unsigned long long acc = 0;
#pragma unroll
        for (int i = 0; i < 32; i++) acc |= (p[i] >> 32);
        s_is64 = (acc == 0ull) ? 1 : 0;
        if (blockIdx.x == 0) {
#pragma unroll
            for (int i = 0; i < NCHUNK; i++) g_flag[i] = 0;
        }
    }
    __syncthreads();
    int e4 = blockIdx.x * blockDim.x + threadIdx.x;
    if (e4 >= NE / 4) return;
    int e = e4 * 4;
    int src[4], dst[4], rel[4];
    if (s_is64) {
        const longlong2* E = (const longlong2*)ei;
        const longlong2* T = (const longlong2*)et;
        longlong2 s0 = __ldg(&E[e / 2]),        s1 = __ldg(&E[e / 2 + 1]);
        longlong2 d0 = __ldg(&E[(NE + e) / 2]), d1 = __ldg(&E[(NE + e) / 2 + 1]);
        longlong2 t0 = __ldg(&T[e / 2]),        t1 = __ldg(&T[e / 2 + 1]);
        src[0] = (int)s0.x; src[1] = (int)s0.y; src[2] = (int)s1.x; src[3] = (int)s1.y;
        dst[0] = (int)d0.x; dst[1] = (int)d0.y; dst[2] = (int)d1.x; dst[3] = (int)d1.y;
        rel[0] = (int)t0.x; rel[1] = (int)t0.y; rel[2] = (int)t1.x; rel[3] = (int)t1.y;
    } else {
        const int* Ei = (const int*)ei;
        const int* Ti = (const int*)et;
        int4 s = __ldg((const int4*)(Ei + e));
        int4 d = __ldg((const int4*)(Ei + NE + e));
        int4 t = __ldg((const int4*)(Ti + e));
        src[0] = s.x; src[1] = s.y; src[2] = s.z; src[3] = s.w;
        dst[0] = d.x; dst[1] = d.y; dst[2] = d.z; dst[3] = d.w;
        rel[0] = t.x; rel[1] = t.y; rel[2] = t.z; rel[3] = t.w;
    }
#pragma unroll
    for (int j = 0; j < 4; j++) {
        int pos = atomicAdd(&g_cur[dst[j]], 1);
        g_csr[pos] = rel[j] * NN + src[j];
    }
}

// Layer-1 aggregation: 16 threads per dst, register accumulation, unroll 8.
__global__ void k_agg1(const float* __restrict__ W1,
                       const float* __restrict__ root1,
                       const float* __restrict__ b1) {
    int g = blockIdx.x * (blockDim.x >> 4) + (threadIdx.x >> 4);
    int s = threadIdx.x & 15;
    if (g >= NN) return;
    int beg = g_off[g], end = g_off[g + 1];

    float4 acc = make_float4(0.f, 0.f, 0.f, 0.f);
    int i = beg;
    for (; i + 8 <= end; i += 8) {
        float4 v0 = __ldg((const float4*)(W1 + (long)g_csr[i + 0] * NH) + s);
        float4 v1 = __ldg((const float4*)(W1 + (long)g_csr[i + 1] * NH) + s);
        float4 v2 = __ldg((const float4*)(W1 + (long)g_csr[i + 2] * NH) + s);
        float4 v3 = __ldg((const float4*)(W1 + (long)g_csr[i + 3] * NH) + s);
        float4 v4 = __ldg((const float4*)(W1 + (long)g_csr[i + 4] * NH) + s);
        float4 v5 = __ldg((const float4*)(W1 + (long)g_csr[i + 5] * NH) + s);
        float4 v6 = __ldg((const float4*)(W1 + (long)g_csr[i + 6] * NH) + s);
        float4 v7 = __ldg((const float4*)(W1 + (long)g_csr[i + 7] * NH) + s);
        acc.x += (v0.x + v1.x) + (v2.x + v3.x) + (v4.x + v5.x) + (v6.x + v7.x);
        acc.y += (v0.y + v1.y) + (v2.y + v3.y) + (v4.y + v5.y) + (v6.y + v7.y);
        acc.z += (v0.z + v1.z) + (v2.z + v3.z) + (v4.z + v5.z) + (v6.z + v7.z);
        acc.w += (v0.w + v1.w) + (v2.w + v3.w) + (v4.w + v5.w) + (v6.w + v7.w);
    }
    for (; i < end; i++) {
        float4 v0 = __ldg((const float4*)(W1 + (long)g_csr[i] * NH) + s);
        acc.x += v0.x; acc.y += v0.y; acc.z += v0.z; acc.w += v0.w;
    }
    float4 rt = __ldg((const float4*)(root1 + (long)g * NH) + s);
    float4 bb = __ldg((const float4*)b1 + s);
    acc.x = fmaxf(acc.x + rt.x + bb.x, 0.f);
    acc.y = fmaxf(acc.y + rt.y + bb.y, 0.f);
    acc.z = fmaxf(acc.z + rt.z + bb.z, 0.f);
    acc.w = fmaxf(acc.w + rt.w + bb.w, 0.f);
    *((float4*)(g_x + (long)g * NH) + s) = acc;
}

// ---------------------------------------------------------------------------
// h[r,n,c] = sum_h x[n,h] * W2[r,h,c]  — f32x2 version.
#define HT 64   // nodes per tile
__global__ void __launch_bounds__(256) k_h2(const float* __restrict__ W2) {
    __shared__ unsigned long long xs[HT * (NH / 2)];   // 16 KB

    int tid  = threadIdx.x;
    int lane = tid & 31;
    int w    = tid >> 5;
    int r    = w * 2 + (lane >> 4);
    int c    = lane & 15;

    unsigned long long wp[NH / 2];
    const float* w2r = W2 + (long)r * NH * NC + c;
#pragma unroll
    for (int j = 0; j < NH / 2; j++) {
        float we = __ldg(w2r + (2 * j) * NC);
        float wo = __ldg(w2r + (2 * j + 1) * NC);
        asm("mov.b64 %0, {%1, %2};" : "=l"(wp[j]) : "f"(we), "f"(wo));
    }

    int nbase = blockIdx.x * HT;
    const unsigned long long* gx8 = (const unsigned long long*)g_x;
    long gbase = (long)nbase * (NH / 2);
    for (int i = tid; i < HT * (NH / 2); i += 256) {
        long gi = gbase + i;
        xs[i] = (gi < (long)NN * (NH / 2)) ? gx8[gi] : 0ull;
    }
    __syncthreads();

    int nvalid = NN - nbase; if (nvalid > HT) nvalid = HT;
    for (int j = 0; j < nvalid; j++) {
        const unsigned long long* xrow = xs + j * (NH / 2);
        unsigned long long a0 = 0ull, a1 = 0ull;
#pragma unroll
        for (int k = 0; k < NH / 4; k++) {
            unsigned long long x0 = xrow[2 * k];
            unsigned long long x1 = xrow[2 * k + 1];
            asm("fma.rn.f32x2 %0, %1, %2, %0;" : "+l"(a0) : "l"(x0), "l"(wp[2 * k]));
            asm("fma.rn.f32x2 %0, %1, %2, %0;" : "+l"(a1) : "l"(x1), "l"(wp[2 * k + 1]));
        }
        unsigned long long asum;
        asm("add.rn.f32x2 %0, %1, %2;" : "=l"(asum) : "l"(a0), "l"(a1));
        float lo, hi;
        asm("mov.b64 {%0, %1}, %2;" : "=f"(lo), "=f"(hi) : "l"(asum));
        g_h[((long)r * NN + (nbase + j)) * NC + c] = lo + hi;
    }
}

// Layer-2 aggregation + root + bias + log_softmax, fused. 16 threads per dst.
__global__ void k_agg2(const float* __restrict__ root2,
                       const float* __restrict__ b2,
                       float* __restrict__ out) {
    __shared__ float r2s[NH * NC];
    for (int i = threadIdx.x; i < NH * NC; i += blockDim.x) r2s[i] = root2[i];
    __syncthreads();

    int g = blockIdx.x * (blockDim.x >> 4) + (threadIdx.x >> 4);
    int c = threadIdx.x & 15;
    if (g >= NN) return;
    int beg = g_off[g], end = g_off[g + 1];

    float acc = __ldg(b2 + c);
    int i = beg;
    for (; i + 8 <= end; i += 8) {
        float v0 = __ldg(g_h + (long)g_csr[i + 0] * NC + c);
        float v1 = __ldg(g_h + (long)g_csr[i + 1] * NC + c);
        float v2 = __ldg(g_h + (long)g_csr[i + 2] * NC + c);
        float v3 = __ldg(g_h + (long)g_csr[i + 3] * NC + c);
        float v4 = __ldg(g_h + (long)g_csr[i + 4] * NC + c);
        float v5 = __ldg(g_h + (long)g_csr[i + 5] * NC + c);
        float v6 = __ldg(g_h + (long)g_csr[i + 6] * NC + c);
        float v7 = __ldg(g_h + (long)g_csr[i + 7] * NC + c);
        acc += ((v0 + v1) + (v2 + v3)) + ((v4 + v5) + (v6 + v7));
    }
    for (; i < end; i++)
        acc += __ldg(g_h + (long)g_csr[i] * NC + c);

    const float4* xr = (const float4*)(g_x + (long)g * NH);
#pragma unroll
    for (int h4 = 0; h4 < NH / 4; h4++) {
        float4 xv = __ldg(&xr[h4]);
        acc += xv.x * r2s[(h4 * 4 + 0) * NC + c];
        acc += xv.y * r2s[(h4 * 4 + 1) * NC + c];
        acc += xv.z * r2s[(h4 * 4 + 2) * NC + c];
        acc += xv.w * r2s[(h4 * 4 + 3) * NC + c];
    }

    unsigned mask = 0xFFFFu << (threadIdx.x & 16);
    float m = acc;
#pragma unroll
    for (int d = 8; d >= 1; d >>= 1) m = fmaxf(m, __shfl_xor_sync(mask, m, d));
    float ex = expf(acc - m);
    float sum = ex;
#pragma unroll
    for (int d = 8; d >= 1; d >>= 1) sum += __shfl_xor_sync(mask, sum, d);
    out[(long)g * NC + c] = acc - m - logf(sum);
}

extern "C" void kernel_launch(void* const* d_in, const int* in_sizes, int n_in,
                              void* d_out, int out_size) {
    const void*  edge_index = d_in[0];
    const void*  edge_type  = d_in[1];
    const float* W1         = (const float*)d_in[2];
    const float* root1      = (const float*)d_in[3];
    const float* b1         = (const float*)d_in[4];
    const float* W2         = (const float*)d_in[5];
    const float* root2      = (const float*)d_in[6];
    const float* b2         = (const float*)d_in[7];
    float* out = (float*)d_out;

    k_hist<<<(NE / 4 + 255) / 256, 256>>>(edge_index);
    k_scan1<<<NCHUNK, 1024>>>();
    k_scatter<<<(NE / 4 + 255) / 256, 256>>>(edge_index, edge_type);
    k_agg1<<<(NN * 16 + 255) / 256, 256>>>(W1, root1, b1);
    k_h2<<<(NN + HT - 1) / HT, 256>>>(W2);
    k_agg2<<<(NN * 16 + 255) / 256, 256>>>(root2, b2, out);
}